// round 12
// baseline (speedup 1.0000x reference)
#include <cuda_runtime.h>
#include <cuda_bf16.h>

// out[n,:] = trace-contraction of the Jacobian of the antisymmetric field
// A(p)=M-M^T (M upper-tri from v=MLP(p), 3->32->32->32->3, softplus beta=20):
//   out0 =  Jv[0][1] + Jv[1][2]
//   out1 = -Jv[0][0] + Jv[2][2]
//   out2 = -Jv[1][0] - Jv[2][1],   Jv[c][j] = dv_c/dx_j
// Forward (sigmoid(20z) diagonals) + 3 simultaneous forward-mode tangents.
//
// R11 = R10 (quarter-warp per sample, 4 samples/warp, blocked smem weights,
// f32x2 K-axis packing) + REGISTER CUT for occupancy: the 36 per-lane-quad
// constants (W1 rows, b1/b2/b3, W4 components) move to a smem table loaded
// per phase as broadcast float4s. Target <=102 regs -> 5 blocks = 20 warps/SM
// (R10 was reg-locked at 16).

#define BETAF 20.0f
#define INV_BETAF 0.05f
#define BLOCK 128
#define WPB (BLOCK / 32)
#define GRID 760   // 152 SMs x 5 resident blocks, persistent loop

typedef unsigned long long ull;

__device__ __forceinline__ ull pk2(float lo, float hi) {
    ull d;
    asm("mov.b64 %0, {%1, %2};" : "=l"(d)
        : "r"(__float_as_uint(lo)), "r"(__float_as_uint(hi)));
    return d;
}
__device__ __forceinline__ float hadd2(ull s) {
    unsigned l, h;
    asm("mov.b64 {%0, %1}, %2;" : "=r"(l), "=r"(h) : "l"(s));
    return __uint_as_float(l) + __uint_as_float(h);
}
#define FMA2(d,a,b,c) asm("fma.rn.f32x2 %0, %1, %2, %3;" : "=l"(d) : "l"(a), "l"(b), "l"(c))

__device__ __forceinline__ void act_hd(float z, float& h, float& d) {
    float y = BETAF * z;
    float e = __expf(-fabsf(y));
    float r = __fdividef(1.0f, 1.0f + e);
    d = (y >= 0.0f) ? r : e * r;                       // sigmoid(20z)
    h = fmaxf(z, 0.0f) + __logf(1.0f + e) * INV_BETAF; // softplus(20z)/20
}
__device__ __forceinline__ float act_d(float z) {
    float y = BETAF * z;
    float e = __expf(-fabsf(y));
    float r = __fdividef(1.0f, 1.0f + e);
    return (y >= 0.0f) ? r : e * r;
}

// fused fwd + 3-tangent chunk c (k-values 4c..4c+3) for one 32x32 layer.
#define CHUNK(WE, WO, HB, TB, c) { \
    const ulonglong2 hv = ((const ulonglong2*)(HB))[c]; \
    const ulonglong2 wA = (WE)[(2*(c)    )*8 + q]; \
    const ulonglong2 wB = (WE)[(2*(c) + 1)*8 + q]; \
    const ulonglong2 wC = (WO)[(2*(c)    )*8 + q]; \
    const ulonglong2 wD = (WO)[(2*(c) + 1)*8 + q]; \
    FMA2(f0, hv.x, wA.x, f0); FMA2(f1, hv.x, wA.y, f1); \
    FMA2(f2, hv.x, wC.x, f2); FMA2(f3, hv.x, wC.y, f3); \
    FMA2(f0, hv.y, wB.x, f0); FMA2(f1, hv.y, wB.y, f1); \
    FMA2(f2, hv.y, wD.x, f2); FMA2(f3, hv.y, wD.y, f3); \
    const ulonglong2 u0 = ((const ulonglong2*)((TB)      ))[c]; \
    const ulonglong2 u1 = ((const ulonglong2*)((TB) + 32 ))[c]; \
    const ulonglong2 u2 = ((const ulonglong2*)((TB) + 64 ))[c]; \
    FMA2(t00,u0.x,wA.x,t00); FMA2(t01,u0.x,wA.y,t01); FMA2(t02,u0.x,wC.x,t02); FMA2(t03,u0.x,wC.y,t03); \
    FMA2(t00,u0.y,wB.x,t00); FMA2(t01,u0.y,wB.y,t01); FMA2(t02,u0.y,wD.x,t02); FMA2(t03,u0.y,wD.y,t03); \
    FMA2(t10,u1.x,wA.x,t10); FMA2(t11,u1.x,wA.y,t11); FMA2(t12,u1.x,wC.x,t12); FMA2(t13,u1.x,wC.y,t13); \
    FMA2(t10,u1.y,wB.x,t10); FMA2(t11,u1.y,wB.y,t11); FMA2(t12,u1.y,wD.x,t12); FMA2(t13,u1.y,wD.y,t13); \
    FMA2(t20,u2.x,wA.x,t20); FMA2(t21,u2.x,wA.y,t21); FMA2(t22,u2.x,wC.x,t22); FMA2(t23,u2.x,wC.y,t23); \
    FMA2(t20,u2.y,wB.x,t20); FMA2(t21,u2.y,wB.y,t21); FMA2(t22,u2.y,wD.x,t22); FMA2(t23,u2.y,wD.y,t23); }

#define LAYER(WE, WO, HB, TB) \
    CHUNK(WE,WO,HB,TB,0) CHUNK(WE,WO,HB,TB,1) CHUNK(WE,WO,HB,TB,2) CHUNK(WE,WO,HB,TB,3) \
    CHUNK(WE,WO,HB,TB,4) CHUNK(WE,WO,HB,TB,5) CHUNK(WE,WO,HB,TB,6) CHUNK(WE,WO,HB,TB,7)

// exchange buffer: per warp 4 samples x 260 floats (1040B stride = 16 mod 128)
#define SMP_F 260
#define WARP_F (4 * SMP_F)

// per-quad constant table: 8 quads x 9 float4 (stride 144B -> q-distinct banks)
// j: 0..2 = W1 rows, 3 = b1, 4 = b2, 5 = b3, 6..8 = W4 components 0..2
#define SC(qq, j) sConst[(qq) * 9 + (j)]

__global__ __launch_bounds__(BLOCK, 5) void NCL_50766513438744_kernel(
    const float* __restrict__ x,
    const float* __restrict__ W1, const float* __restrict__ b1,
    const float* __restrict__ W2, const float* __restrict__ b2,
    const float* __restrict__ W3, const float* __restrict__ b3,
    const float* __restrict__ W4,
    float* __restrict__ out, int N, int totalWarps)
{
    __shared__ __align__(16) ulonglong2 sW2E[128], sW2O[128], sW3E[128], sW3O[128];
    __shared__ __align__(16) float4 sConst[72];
    __shared__ __align__(16) float sBuf[WPB * WARP_F];

    {
        const int t = threadIdx.x;
        const int i = t >> 3, qq = t & 7;
        const int c0 = 4 * qq;
        float4 v;
        v = make_float4(W2[(2*i)*32 + c0],     W2[(2*i+1)*32 + c0],
                        W2[(2*i)*32 + c0 + 1], W2[(2*i+1)*32 + c0 + 1]);
        ((float4*)sW2E)[t] = v;
        v = make_float4(W2[(2*i)*32 + c0 + 2], W2[(2*i+1)*32 + c0 + 2],
                        W2[(2*i)*32 + c0 + 3], W2[(2*i+1)*32 + c0 + 3]);
        ((float4*)sW2O)[t] = v;
        v = make_float4(W3[(2*i)*32 + c0],     W3[(2*i+1)*32 + c0],
                        W3[(2*i)*32 + c0 + 1], W3[(2*i+1)*32 + c0 + 1]);
        ((float4*)sW3E)[t] = v;
        v = make_float4(W3[(2*i)*32 + c0 + 2], W3[(2*i+1)*32 + c0 + 2],
                        W3[(2*i)*32 + c0 + 3], W3[(2*i+1)*32 + c0 + 3]);
        ((float4*)sW3O)[t] = v;

        if (t < 72) {
            const int qc = t / 9, j = t % 9;
            const int cbq = 4 * qc;
            float4 cv;
            if (j < 3)       cv = make_float4(W1[j*32+cbq], W1[j*32+cbq+1], W1[j*32+cbq+2], W1[j*32+cbq+3]);
            else if (j == 3) cv = make_float4(b1[cbq], b1[cbq+1], b1[cbq+2], b1[cbq+3]);
            else if (j == 4) cv = make_float4(b2[cbq], b2[cbq+1], b2[cbq+2], b2[cbq+3]);
            else if (j == 5) cv = make_float4(b3[cbq], b3[cbq+1], b3[cbq+2], b3[cbq+3]);
            else { const int comp = j - 6;
                   cv = make_float4(W4[(cbq+0)*3+comp], W4[(cbq+1)*3+comp],
                                    W4[(cbq+2)*3+comp], W4[(cbq+3)*3+comp]); }
            sConst[t] = cv;
        }
    }
    __syncthreads();

    const int lane = threadIdx.x & 31;
    const int wib  = threadIdx.x >> 5;
    const int smp  = lane >> 3;          // sample slot 0..3
    const int q    = lane & 7;           // column quad: cols 4q..4q+3

    float* const sb  = &sBuf[wib * WARP_F + smp * SMP_F];
    float* const hb1 = sb;               // h1 [32]
    float* const hb2 = sb + 32;          // h2 [32]
    float* const tb1 = sb + 64;          // t1 [3][32]
    float* const tb2 = sb + 160;         // t2 [3][32]

    const int nGroups = (N + 3) >> 2;
    const int gw = blockIdx.x * WPB + wib;
    if (gw >= nGroups) return;

    int myIdx = 4 * gw + smp; if (myIdx >= N) myIdx = N - 1;
    float x0 = __ldg(x + 3 * myIdx + 0);
    float x1 = __ldg(x + 3 * myIdx + 1);
    float x2 = __ldg(x + 3 * myIdx + 2);

    for (int g = gw; g < nGroups; g += totalWarps) {
        const int sIdx = 4 * g + smp;

        // ===== phase A: layer 1 + tangent seeds for 4 columns =====
        {
            const float4 wa = SC(q, 0), wb = SC(q, 1), wc = SC(q, 2), bq = SC(q, 3);
            float h0, h1v, h2v, h3v, d0, d1v, d2v, d3v;
            act_hd(fmaf(x0, wa.x, fmaf(x1, wb.x, fmaf(x2, wc.x, bq.x))), h0,  d0);
            act_hd(fmaf(x0, wa.y, fmaf(x1, wb.y, fmaf(x2, wc.y, bq.y))), h1v, d1v);
            act_hd(fmaf(x0, wa.z, fmaf(x1, wb.z, fmaf(x2, wc.z, bq.z))), h2v, d2v);
            act_hd(fmaf(x0, wa.w, fmaf(x1, wb.w, fmaf(x2, wc.w, bq.w))), h3v, d3v);
            ((float4*)hb1)[q] = make_float4(h0, h1v, h2v, h3v);
            ((float4*)(tb1     ))[q] = make_float4(d0*wa.x, d1v*wa.y, d2v*wa.z, d3v*wa.w);
            ((float4*)(tb1 + 32))[q] = make_float4(d0*wb.x, d1v*wb.y, d2v*wb.z, d3v*wb.w);
            ((float4*)(tb1 + 64))[q] = make_float4(d0*wc.x, d1v*wc.y, d2v*wc.z, d3v*wc.w);
        }
        __syncwarp();

        // prefetch next group's x
        {
            const int gn = g + totalWarps;
            int nIdx = 4 * gn + smp;
            if (nIdx >= N) nIdx = N - 1;
            x0 = __ldg(x + 3 * nIdx + 0);
            x1 = __ldg(x + 3 * nIdx + 1);
            x2 = __ldg(x + 3 * nIdx + 2);
        }

        // ===== phase B: layer-2 forward + tangent layer 2 =====
        ull f0, f1, f2, f3;
        {
            const float4 bq = SC(q, 4);
            f0 = pk2(bq.x, 0.f); f1 = pk2(bq.y, 0.f); f2 = pk2(bq.z, 0.f); f3 = pk2(bq.w, 0.f);
        }
        ull t00=0ull,t01=0ull,t02=0ull,t03=0ull,
            t10=0ull,t11=0ull,t12=0ull,t13=0ull,
            t20=0ull,t21=0ull,t22=0ull,t23=0ull;
        LAYER(sW2E, sW2O, hb1, tb1)
        {
            float h0, h1v, h2v, h3v, d0, d1v, d2v, d3v;
            act_hd(hadd2(f0), h0,  d0);
            act_hd(hadd2(f1), h1v, d1v);
            act_hd(hadd2(f2), h2v, d2v);
            act_hd(hadd2(f3), h3v, d3v);
            ((float4*)hb2)[q] = make_float4(h0, h1v, h2v, h3v);
            ((float4*)(tb2     ))[q] = make_float4(d0*hadd2(t00), d1v*hadd2(t01), d2v*hadd2(t02), d3v*hadd2(t03));
            ((float4*)(tb2 + 32))[q] = make_float4(d0*hadd2(t10), d1v*hadd2(t11), d2v*hadd2(t12), d3v*hadd2(t13));
            ((float4*)(tb2 + 64))[q] = make_float4(d0*hadd2(t20), d1v*hadd2(t21), d2v*hadd2(t22), d3v*hadd2(t23));
        }
        __syncwarp();

        // ===== phase C: layer-3 forward (deriv only) + tangent layer 3 =====
        {
            const float4 bq = SC(q, 5);
            f0 = pk2(bq.x, 0.f); f1 = pk2(bq.y, 0.f); f2 = pk2(bq.z, 0.f); f3 = pk2(bq.w, 0.f);
        }
        t00=0ull;t01=0ull;t02=0ull;t03=0ull;
        t10=0ull;t11=0ull;t12=0ull;t13=0ull;
        t20=0ull;t21=0ull;t22=0ull;t23=0ull;
        LAYER(sW3E, sW3O, hb2, tb2)
        {
            const float d0  = act_d(hadd2(f0));
            const float d1v = act_d(hadd2(f1));
            const float d2v = act_d(hadd2(f2));
            const float d3v = act_d(hadd2(f3));
            const float s00 = d0*hadd2(t00), s01 = d1v*hadd2(t01), s02 = d2v*hadd2(t02), s03 = d3v*hadd2(t03);
            const float s10 = d0*hadd2(t10), s11 = d1v*hadd2(t11), s12 = d2v*hadd2(t12), s13 = d3v*hadd2(t13);
            const float s20 = d0*hadd2(t20), s21 = d1v*hadd2(t21), s22 = d2v*hadd2(t22), s23 = d3v*hadd2(t23);

            const float4 w40 = SC(q, 6), w41 = SC(q, 7), w42 = SC(q, 8);
            float po0 = fmaf(s10, w40.x, s20 * w41.x)
                      + fmaf(s11, w40.y, s21 * w41.y)
                      + fmaf(s12, w40.z, s22 * w41.z)
                      + fmaf(s13, w40.w, s23 * w41.w);
            float po1 = fmaf(s20, w42.x, -(s00 * w40.x))
                      + fmaf(s21, w42.y, -(s01 * w40.y))
                      + fmaf(s22, w42.z, -(s02 * w40.z))
                      + fmaf(s23, w42.w, -(s03 * w40.w));
            float po2 = -(fmaf(s00, w41.x, s10 * w42.x)
                        + fmaf(s01, w41.y, s11 * w42.y)
                        + fmaf(s02, w41.z, s12 * w42.z)
                        + fmaf(s03, w41.w, s13 * w42.w));

            #pragma unroll
            for (int off = 4; off; off >>= 1) {
                po0 += __shfl_xor_sync(0xffffffffu, po0, off);
                po1 += __shfl_xor_sync(0xffffffffu, po1, off);
                po2 += __shfl_xor_sync(0xffffffffu, po2, off);
            }
            if (q == 0 && sIdx < N) {
                out[3 * sIdx + 0] = po0;
                out[3 * sIdx + 1] = po1;
                out[3 * sIdx + 2] = po2;
            }
        }
        // loop-carried buffer hazards covered by the two syncwarps per iter
    }
}

extern "C" void kernel_launch(void* const* d_in, const int* in_sizes, int n_in,
                              void* d_out, int out_size) {
    const float* x  = (const float*)d_in[0];
    const float* W1 = (const float*)d_in[1];
    const float* b1 = (const float*)d_in[2];
    const float* W2 = (const float*)d_in[3];
    const float* b2 = (const float*)d_in[4];
    const float* W3 = (const float*)d_in[5];
    const float* b3 = (const float*)d_in[6];
    const float* W4 = (const float*)d_in[7];
    // d_in[8] = b4: not needed (bias drops out of the Jacobian)
    float* out = (float*)d_out;

    const int N = in_sizes[0] / 3;
    const int totalWarps = GRID * WPB;
    NCL_50766513438744_kernel<<<GRID, BLOCK>>>(x, W1, b1, W2, b2, W3, b3, W4,
                                               out, N, totalWarps);
}

// round 14
// speedup vs baseline: 1.0938x; 1.0938x over previous
#include <cuda_runtime.h>
#include <cuda_bf16.h>

// out[n,:] = trace-contraction of the Jacobian of the antisymmetric field
// A(p)=M-M^T (M upper-tri from v=MLP(p), 3->32->32->32->3, softplus beta=20):
//   out0 =  Jv[0][1] + Jv[1][2]
//   out1 = -Jv[0][0] + Jv[2][2]
//   out2 = -Jv[1][0] - Jv[2][1],   Jv[c][j] = dv_c/dx_j
// Forward (sigmoid(20z) diagonals) + 3 simultaneous forward-mode tangents.
//
// R13 = R12 (8 samples/warp, lane owns 8 cols, blocked smem weights, f32x2
// K-packing) with the macro name-capture bug fixed: tangent accumulator banks
// are now pa*/pb*/pc* — they no longer collide with the smem pointers tb1/tb2
// (R12's KP macro overwrote the pointers via asm outputs -> illegal access).

#define BETAF 20.0f
#define INV_BETAF 0.05f
#define BLOCK 96
#define WPB (BLOCK / 32)
#define GRID 608   // 152 SMs x 4 resident blocks, persistent loop

typedef unsigned long long ull;

__device__ __forceinline__ ull pk2(float lo, float hi) {
    ull d;
    asm("mov.b64 %0, {%1, %2};" : "=l"(d)
        : "r"(__float_as_uint(lo)), "r"(__float_as_uint(hi)));
    return d;
}
__device__ __forceinline__ float hadd2(ull s) {
    unsigned l, h;
    asm("mov.b64 {%0, %1}, %2;" : "=r"(l), "=r"(h) : "l"(s));
    return __uint_as_float(l) + __uint_as_float(h);
}
#define FMA2(d,a,b,c) asm("fma.rn.f32x2 %0, %1, %2, %3;" : "=l"(d) : "l"(a), "l"(b), "l"(c))

__device__ __forceinline__ void act_hd(float z, float& h, float& d) {
    float y = BETAF * z;
    float e = __expf(-fabsf(y));
    float r = __fdividef(1.0f, 1.0f + e);
    d = (y >= 0.0f) ? r : e * r;                       // sigmoid(20z)
    h = fmaxf(z, 0.0f) + __logf(1.0f + e) * INV_BETAF; // softplus(20z)/20
}
__device__ __forceinline__ float act_d(float z) {
    float y = BETAF * z;
    float e = __expf(-fabsf(y));
    float r = __fdividef(1.0f, 1.0f + e);
    return (y >= 0.0f) ? r : e * r;
}

// one k-pair micro-step: 4 LDS.128 of weights (8 cols), 32 FMA2.
// Accumulators: forward f0..f7; tangents pa0..pa7 / pb0..pb7 / pc0..pc7.
#define KP(WB, kp, hvh, u0h, u1h, u2h) { \
    const ulonglong2* wp_ = (const ulonglong2*)((WB) + ((kp)*4 + q)*10); \
    const ulonglong2 wa = wp_[0], wb = wp_[1], wc = wp_[2], wd = wp_[3]; \
    FMA2(f0,hvh,wa.x,f0); FMA2(f1,hvh,wa.y,f1); FMA2(f2,hvh,wb.x,f2); FMA2(f3,hvh,wb.y,f3); \
    FMA2(f4,hvh,wc.x,f4); FMA2(f5,hvh,wc.y,f5); FMA2(f6,hvh,wd.x,f6); FMA2(f7,hvh,wd.y,f7); \
    FMA2(pa0,u0h,wa.x,pa0); FMA2(pa1,u0h,wa.y,pa1); FMA2(pa2,u0h,wb.x,pa2); FMA2(pa3,u0h,wb.y,pa3); \
    FMA2(pa4,u0h,wc.x,pa4); FMA2(pa5,u0h,wc.y,pa5); FMA2(pa6,u0h,wd.x,pa6); FMA2(pa7,u0h,wd.y,pa7); \
    FMA2(pb0,u1h,wa.x,pb0); FMA2(pb1,u1h,wa.y,pb1); FMA2(pb2,u1h,wb.x,pb2); FMA2(pb3,u1h,wb.y,pb3); \
    FMA2(pb4,u1h,wc.x,pb4); FMA2(pb5,u1h,wc.y,pb5); FMA2(pb6,u1h,wd.x,pb6); FMA2(pb7,u1h,wd.y,pb7); \
    FMA2(pc0,u2h,wa.x,pc0); FMA2(pc1,u2h,wa.y,pc1); FMA2(pc2,u2h,wb.x,pc2); FMA2(pc3,u2h,wb.y,pc3); \
    FMA2(pc4,u2h,wc.x,pc4); FMA2(pc5,u2h,wc.y,pc5); FMA2(pc6,u2h,wd.x,pc6); FMA2(pc7,u2h,wd.y,pc7); }

// chunk c = k-values 4c..4c+3 : 4 exchange LDS.128 + 2 KP steps
#define CHUNK(WB, HB, TB, c) { \
    const ulonglong2 hv = ((const ulonglong2*)(HB))[c]; \
    const ulonglong2 u0 = ((const ulonglong2*)((TB)     ))[c]; \
    const ulonglong2 u1 = ((const ulonglong2*)((TB) + 32))[c]; \
    const ulonglong2 u2 = ((const ulonglong2*)((TB) + 64))[c]; \
    KP(WB, 2*(c),     hv.x, u0.x, u1.x, u2.x) \
    KP(WB, 2*(c) + 1, hv.y, u0.y, u1.y, u2.y) }

#define LAYER(WB, HB, TB) \
    CHUNK(WB,HB,TB,0) CHUNK(WB,HB,TB,1) CHUNK(WB,HB,TB,2) CHUNK(WB,HB,TB,3) \
    CHUNK(WB,HB,TB,4) CHUNK(WB,HB,TB,5) CHUNK(WB,HB,TB,6) CHUNK(WB,HB,TB,7)

#define ZERO_T() \
    pa0=0ull;pa1=0ull;pa2=0ull;pa3=0ull;pa4=0ull;pa5=0ull;pa6=0ull;pa7=0ull; \
    pb0=0ull;pb1=0ull;pb2=0ull;pb3=0ull;pb4=0ull;pb5=0ull;pb6=0ull;pb7=0ull; \
    pc0=0ull;pc1=0ull;pc2=0ull;pc3=0ull;pc4=0ull;pc5=0ull;pc6=0ull;pc7=0ull;

// exchange: 8 samples x 260 floats (1040B stride, = 16 mod 128)
#define SMP_F 260
#define WARP_F (8 * SMP_F)

__global__ __launch_bounds__(BLOCK, 4) void NCL_50766513438744_kernel(
    const float* __restrict__ x,
    const float* __restrict__ W1, const float* __restrict__ b1,
    const float* __restrict__ W2, const float* __restrict__ b2,
    const float* __restrict__ W3, const float* __restrict__ b3,
    const float* __restrict__ W4,
    float* __restrict__ out, int N, int totalWarps)
{
    // blocked weights: (kp,q) block = 8 ulls (cols 8q..8q+7 as (W[2kp][c],W[2kp+1][c])),
    // padded to 10 ulls (80B) so the 4 q-addresses hit distinct bank groups
    __shared__ __align__(16) ull sW2u[640], sW3u[640];
    // const tables: W1 rows (96), biases b1/b2/b3 (96), W4 components (96)
    __shared__ __align__(16) float sCW1[96], sCB[96], sCW4[96];
    __shared__ __align__(16) float sBuf[WPB * WARP_F];

    {
        const int t = threadIdx.x;
        for (int idx = t; idx < 1024; idx += BLOCK) {
            const int k = idx >> 5, m = idx & 31;
            const int uidx = ((k >> 1) * 4 + (m >> 3)) * 10 + (m & 7);
            const int fidx = uidx * 2 + (k & 1);
            ((float*)sW2u)[fidx] = W2[idx];
            ((float*)sW3u)[fidx] = W3[idx];
        }
        if (t < 32) {
            sCW1[t] = W1[t]; sCW1[32 + t] = W1[32 + t]; sCW1[64 + t] = W1[64 + t];
            sCB[t] = b1[t];  sCB[32 + t] = b2[t];       sCB[64 + t] = b3[t];
            sCW4[t] = W4[t * 3 + 0]; sCW4[32 + t] = W4[t * 3 + 1]; sCW4[64 + t] = W4[t * 3 + 2];
        }
    }
    __syncthreads();

    const int lane = threadIdx.x & 31;
    const int wib  = threadIdx.x >> 5;
    const int smp  = lane >> 2;          // sample slot 0..7
    const int q    = lane & 3;           // column octet: cols 8q..8q+7

    float* const sb  = &sBuf[wib * WARP_F + smp * SMP_F];
    float* const hb1 = sb;               // h1 [32]
    float* const hb2 = sb + 32;          // h2 [32]
    float* const tb1 = sb + 64;          // t1 [3][32]
    float* const tb2 = sb + 160;         // t2 [3][32]

    const float4* const F4W1 = (const float4*)sCW1;
    const float4* const F4B  = (const float4*)sCB;
    const float4* const F4W4 = (const float4*)sCW4;

    const int nGroups = (N + 7) >> 3;
    const int gw = blockIdx.x * WPB + wib;
    if (gw >= nGroups) return;

    int myIdx = 8 * gw + smp; if (myIdx >= N) myIdx = N - 1;
    float x0 = __ldg(x + 3 * myIdx + 0);
    float x1 = __ldg(x + 3 * myIdx + 1);
    float x2 = __ldg(x + 3 * myIdx + 2);

    for (int g = gw; g < nGroups; g += totalWarps) {
        const int sIdx = 8 * g + smp;

        // ===== phase A: layer 1 + tangent seeds for this lane's 8 columns =====
        {
            const float4 r0a = F4W1[2*q],      r0b = F4W1[2*q + 1];
            const float4 r1a = F4W1[8 + 2*q],  r1b = F4W1[9 + 2*q];
            const float4 r2a = F4W1[16 + 2*q], r2b = F4W1[17 + 2*q];
            const float4 ba  = F4B[2*q],       bb  = F4B[2*q + 1];
            float4 h4a, h4b, d4a, d4b;
#define L1C(M, RA, RB, RC, BB, HD, DD) { float z_ = fmaf(x0, RA.M, fmaf(x1, RB.M, fmaf(x2, RC.M, BB.M))); \
                                         act_hd(z_, HD.M, DD.M); }
            L1C(x, r0a, r1a, r2a, ba, h4a, d4a) L1C(y, r0a, r1a, r2a, ba, h4a, d4a)
            L1C(z, r0a, r1a, r2a, ba, h4a, d4a) L1C(w, r0a, r1a, r2a, ba, h4a, d4a)
            L1C(x, r0b, r1b, r2b, bb, h4b, d4b) L1C(y, r0b, r1b, r2b, bb, h4b, d4b)
            L1C(z, r0b, r1b, r2b, bb, h4b, d4b) L1C(w, r0b, r1b, r2b, bb, h4b, d4b)
#undef L1C
            ((float4*)hb1)[2*q]     = h4a;
            ((float4*)hb1)[2*q + 1] = h4b;
            ((float4*)tb1)[2*q]      = make_float4(d4a.x*r0a.x, d4a.y*r0a.y, d4a.z*r0a.z, d4a.w*r0a.w);
            ((float4*)tb1)[2*q + 1]  = make_float4(d4b.x*r0b.x, d4b.y*r0b.y, d4b.z*r0b.z, d4b.w*r0b.w);
            ((float4*)tb1)[8 + 2*q]  = make_float4(d4a.x*r1a.x, d4a.y*r1a.y, d4a.z*r1a.z, d4a.w*r1a.w);
            ((float4*)tb1)[9 + 2*q]  = make_float4(d4b.x*r1b.x, d4b.y*r1b.y, d4b.z*r1b.z, d4b.w*r1b.w);
            ((float4*)tb1)[16 + 2*q] = make_float4(d4a.x*r2a.x, d4a.y*r2a.y, d4a.z*r2a.z, d4a.w*r2a.w);
            ((float4*)tb1)[17 + 2*q] = make_float4(d4b.x*r2b.x, d4b.y*r2b.y, d4b.z*r2b.z, d4b.w*r2b.w);
        }
        __syncwarp();

        // prefetch next group's x
        {
            const int gn = g + totalWarps;
            int nIdx = 8 * gn + smp;
            if (nIdx >= N) nIdx = N - 1;
            x0 = __ldg(x + 3 * nIdx + 0);
            x1 = __ldg(x + 3 * nIdx + 1);
            x2 = __ldg(x + 3 * nIdx + 2);
        }

        // ===== phase B: layer-2 forward + tangent layer 2 =====
        ull f0, f1, f2, f3, f4, f5, f6, f7;
        {
            const float4 ba = F4B[8 + 2*q], bb = F4B[9 + 2*q];   // b2
            f0 = pk2(ba.x, 0.f); f1 = pk2(ba.y, 0.f); f2 = pk2(ba.z, 0.f); f3 = pk2(ba.w, 0.f);
            f4 = pk2(bb.x, 0.f); f5 = pk2(bb.y, 0.f); f6 = pk2(bb.z, 0.f); f7 = pk2(bb.w, 0.f);
        }
        ull pa0,pa1,pa2,pa3,pa4,pa5,pa6,pa7,
            pb0,pb1,pb2,pb3,pb4,pb5,pb6,pb7,
            pc0,pc1,pc2,pc3,pc4,pc5,pc6,pc7;
        ZERO_T()
        LAYER(sW2u, hb1, tb1)
        {
            float4 h4a, h4b, d4a, d4b;
#define ACTB(M, FF, HD, DD) { float z_ = hadd2(FF); act_hd(z_, HD.M, DD.M); }
            ACTB(x, f0, h4a, d4a) ACTB(y, f1, h4a, d4a) ACTB(z, f2, h4a, d4a) ACTB(w, f3, h4a, d4a)
            ACTB(x, f4, h4b, d4b) ACTB(y, f5, h4b, d4b) ACTB(z, f6, h4b, d4b) ACTB(w, f7, h4b, d4b)
#undef ACTB
            ((float4*)hb2)[2*q]     = h4a;
            ((float4*)hb2)[2*q + 1] = h4b;
            ((float4*)tb2)[2*q]      = make_float4(d4a.x*hadd2(pa0), d4a.y*hadd2(pa1), d4a.z*hadd2(pa2), d4a.w*hadd2(pa3));
            ((float4*)tb2)[2*q + 1]  = make_float4(d4b.x*hadd2(pa4), d4b.y*hadd2(pa5), d4b.z*hadd2(pa6), d4b.w*hadd2(pa7));
            ((float4*)tb2)[8 + 2*q]  = make_float4(d4a.x*hadd2(pb0), d4a.y*hadd2(pb1), d4a.z*hadd2(pb2), d4a.w*hadd2(pb3));
            ((float4*)tb2)[9 + 2*q]  = make_float4(d4b.x*hadd2(pb4), d4b.y*hadd2(pb5), d4b.z*hadd2(pb6), d4b.w*hadd2(pb7));
            ((float4*)tb2)[16 + 2*q] = make_float4(d4a.x*hadd2(pc0), d4a.y*hadd2(pc1), d4a.z*hadd2(pc2), d4a.w*hadd2(pc3));
            ((float4*)tb2)[17 + 2*q] = make_float4(d4b.x*hadd2(pc4), d4b.y*hadd2(pc5), d4b.z*hadd2(pc6), d4b.w*hadd2(pc7));
        }
        __syncwarp();

        // ===== phase C: layer-3 forward (deriv only) + tangent layer 3 =====
        {
            const float4 ba = F4B[16 + 2*q], bb = F4B[17 + 2*q];  // b3
            f0 = pk2(ba.x, 0.f); f1 = pk2(ba.y, 0.f); f2 = pk2(ba.z, 0.f); f3 = pk2(ba.w, 0.f);
            f4 = pk2(bb.x, 0.f); f5 = pk2(bb.y, 0.f); f6 = pk2(bb.z, 0.f); f7 = pk2(bb.w, 0.f);
        }
        ZERO_T()
        LAYER(sW3u, hb2, tb2)
        {
            const float dd0 = act_d(hadd2(f0)), dd1 = act_d(hadd2(f1));
            const float dd2 = act_d(hadd2(f2)), dd3 = act_d(hadd2(f3));
            const float dd4 = act_d(hadd2(f4)), dd5 = act_d(hadd2(f5));
            const float dd6 = act_d(hadd2(f6)), dd7 = act_d(hadd2(f7));
            const float4 s0a = make_float4(dd0*hadd2(pa0), dd1*hadd2(pa1), dd2*hadd2(pa2), dd3*hadd2(pa3));
            const float4 s0b = make_float4(dd4*hadd2(pa4), dd5*hadd2(pa5), dd6*hadd2(pa6), dd7*hadd2(pa7));
            const float4 s1a = make_float4(dd0*hadd2(pb0), dd1*hadd2(pb1), dd2*hadd2(pb2), dd3*hadd2(pb3));
            const float4 s1b = make_float4(dd4*hadd2(pb4), dd5*hadd2(pb5), dd6*hadd2(pb6), dd7*hadd2(pb7));
            const float4 s2a = make_float4(dd0*hadd2(pc0), dd1*hadd2(pc1), dd2*hadd2(pc2), dd3*hadd2(pc3));
            const float4 s2b = make_float4(dd4*hadd2(pc4), dd5*hadd2(pc5), dd6*hadd2(pc6), dd7*hadd2(pc7));

            const float4 w0a = F4W4[2*q],      w0b = F4W4[2*q + 1];
            const float4 w1a = F4W4[8 + 2*q],  w1b = F4W4[9 + 2*q];
            const float4 w2a = F4W4[16 + 2*q], w2b = F4W4[17 + 2*q];

            float po0 = 0.f, po1 = 0.f, po2 = 0.f;
#define CONTRIB(S0, S1, S2, WA, WB, WC, M) \
            po0 += fmaf(S1.M, WA.M, S2.M * WB.M); \
            po1 += fmaf(S2.M, WC.M, -(S0.M * WA.M)); \
            po2 -= fmaf(S0.M, WB.M, S1.M * WC.M);
            CONTRIB(s0a, s1a, s2a, w0a, w1a, w2a, x)
            CONTRIB(s0a, s1a, s2a, w0a, w1a, w2a, y)
            CONTRIB(s0a, s1a, s2a, w0a, w1a, w2a, z)
            CONTRIB(s0a, s1a, s2a, w0a, w1a, w2a, w)
            CONTRIB(s0b, s1b, s2b, w0b, w1b, w2b, x)
            CONTRIB(s0b, s1b, s2b, w0b, w1b, w2b, y)
            CONTRIB(s0b, s1b, s2b, w0b, w1b, w2b, z)
            CONTRIB(s0b, s1b, s2b, w0b, w1b, w2b, w)
#undef CONTRIB
            // reduce over the 4 lanes of this sample's quartet
            po0 += __shfl_xor_sync(0xffffffffu, po0, 1);
            po1 += __shfl_xor_sync(0xffffffffu, po1, 1);
            po2 += __shfl_xor_sync(0xffffffffu, po2, 1);
            po0 += __shfl_xor_sync(0xffffffffu, po0, 2);
            po1 += __shfl_xor_sync(0xffffffffu, po1, 2);
            po2 += __shfl_xor_sync(0xffffffffu, po2, 2);
            if (q == 0 && sIdx < N) {
                out[3 * sIdx + 0] = po0;
                out[3 * sIdx + 1] = po1;
                out[3 * sIdx + 2] = po2;
            }
        }
        // loop-carried buffer hazards covered by the two syncwarps per iter
    }
}

extern "C" void kernel_launch(void* const* d_in, const int* in_sizes, int n_in,
                              void* d_out, int out_size) {
    const float* x  = (const float*)d_in[0];
    const float* W1 = (const float*)d_in[1];
    const float* b1 = (const float*)d_in[2];
    const float* W2 = (const float*)d_in[3];
    const float* b2 = (const float*)d_in[4];
    const float* W3 = (const float*)d_in[5];
    const float* b3 = (const float*)d_in[6];
    const float* W4 = (const float*)d_in[7];
    // d_in[8] = b4: not needed (bias drops out of the Jacobian)
    float* out = (float*)d_out;

    const int N = in_sizes[0] / 3;
    const int totalWarps = GRID * WPB;
    NCL_50766513438744_kernel<<<GRID, BLOCK>>>(x, W1, b1, W2, b2, W3, b3, W4,
                                               out, N, totalWarps);
}